// round 2
// baseline (speedup 1.0000x reference)
#include <cuda_runtime.h>

// AudioLSTM: 2-layer LSTM (26 -> 64 -> 32) over T=1000, B=512, + FC 32->16->10.
// One CTA per batch element. Weights register-resident. fma.rn.f32x2 packed math.
// Layer 2 lags layer 1 by one step -> 2 barriers per timestep.

#define IN   26
#define H1   64
#define H2   32
#define NB   512
#define TT   1000
#define NTHREADS 384

typedef unsigned long long ull;

__device__ __forceinline__ ull pack2(float lo, float hi) {
    ull r;
    asm("mov.b64 %0, {%1, %2};" : "=l"(r) : "f"(lo), "f"(hi));
    return r;
}
__device__ __forceinline__ float sum2(ull a) {
    float lo, hi;
    asm("mov.b64 {%0, %1}, %2;" : "=f"(lo), "=f"(hi) : "l"(a));
    return lo + hi;
}
__device__ __forceinline__ ull fma2(ull a, ull b, ull c) {
    ull d;
    asm("fma.rn.f32x2 %0, %1, %2, %3;" : "=l"(d) : "l"(a), "l"(b), "l"(c));
    return d;
}
__device__ __forceinline__ ull add2(ull a, ull b) {
    ull d;
    asm("add.rn.f32x2 %0, %1, %2;" : "=l"(d) : "l"(a), "l"(b));
    return d;
}

// bar.sync 0 executed from both specialization branches; arrival counts match
// per iteration across branches (warp-specialization pattern, sm_70+).
#define BARSYNC() asm volatile("bar.sync 0;" ::: "memory")

__device__ __forceinline__ float sigmoid_fast(float x) {
    float e = __expf(-x);                      // MUFU.EX2 path
    return __fdividef(1.0f, 1.0f + e);         // MUFU.RCP path
}
__device__ __forceinline__ float tanh_fast(float x) {
    // tanh(x) = 2/(1+exp(-2x)) - 1 ; saturates correctly at +/-inf
    float e = __expf(-2.0f * x);
    return __fmaf_rn(2.0f, __fdividef(1.0f, 1.0f + e), -1.0f);
}

__global__ void __launch_bounds__(NTHREADS, 1)
audiolstm_kernel(const float* __restrict__ x,
                 const float* __restrict__ w_ih1, const float* __restrict__ w_hh1,
                 const float* __restrict__ b_ih1, const float* __restrict__ b_hh1,
                 const float* __restrict__ w_ih2, const float* __restrict__ w_hh2,
                 const float* __restrict__ b_ih2, const float* __restrict__ b_hh2,
                 const float* __restrict__ w_fc1, const float* __restrict__ b_fc1,
                 const float* __restrict__ w_fc2, const float* __restrict__ b_fc2,
                 float* __restrict__ out)
{
    const int b   = blockIdx.x;
    const int tid = threadIdx.x;

    __shared__ __align__(16) float sh1[H1];        // h1(t)
    __shared__ __align__(16) float sh2[H2];        // h2(t)
    __shared__ __align__(16) float sg1[4 * H1];    // activated gates, layer 1
    __shared__ __align__(16) float sg2[4 * H2];    // activated gates, layer 2
    __shared__ __align__(16) float sx[2][IN + 2];  // x(t) double buffer (pad keeps 8B align)
    __shared__ __align__(16) float sf[16];         // fc1 output

    const size_t xbase = (size_t)b * (size_t)(IN * TT);

    // ---- init (before first barrier) ----
    if (tid < H1) sh1[tid] = 0.0f;
    if (tid < H2) sh2[tid] = 0.0f;
    if (tid >= 96 && tid < 96 + IN) {
        int i = tid - 96;
        sx[0][i] = x[xbase + (size_t)i * TT + 0];
    }

    if (tid < 256) {
        // ================= Layer-1 gate thread (also phase-2 roles) ==============
        ull wih[13], whh[32];
        {
            const float2* wi = (const float2*)(w_ih1 + tid * IN);   // 104B rows: 8B aligned
            #pragma unroll
            for (int k = 0; k < 13; k++) { float2 v = wi[k]; wih[k] = pack2(v.x, v.y); }
            const float2* wh = (const float2*)(w_hh1 + tid * H1);
            #pragma unroll
            for (int k = 0; k < 32; k++) { float2 v = wh[k]; whh[k] = pack2(v.x, v.y); }
        }
        const float bias = b_ih1[tid] + b_hh1[tid];
        const int   cls  = tid >> 6;           // 0:i 1:f 2:g 3:o (uniform per warp)

        const bool is_upd1 = (tid < 64);
        const bool is_upd2 = (tid >= 64 && tid < 96);
        const bool is_load = (tid >= 96 && tid < 96 + IN);
        const int  xi      = tid - 96;

        float c1 = 0.0f, c2 = 0.0f;
        float xreg = 0.0f;
        if (is_load) xreg = x[xbase + (size_t)xi * TT + 1];

        #pragma unroll 1
        for (int t = 0; t <= TT; t++) {
            BARSYNC();  // A: sh1(t-1), sh2(t-2), sx[t&1] ready
            if (t < TT) {
                ull a0 = pack2(bias, 0.0f), a1 = 0ull, a2 = 0ull, a3 = 0ull;
                const ull* hp = (const ull*)sh1;
                #pragma unroll
                for (int k = 0; k < 32; k += 4) {
                    a0 = fma2(hp[k + 0], whh[k + 0], a0);
                    a1 = fma2(hp[k + 1], whh[k + 1], a1);
                    a2 = fma2(hp[k + 2], whh[k + 2], a2);
                    a3 = fma2(hp[k + 3], whh[k + 3], a3);
                }
                const ull* xp = (const ull*)sx[t & 1];
                #pragma unroll
                for (int k = 0; k < 12; k += 4) {
                    a0 = fma2(xp[k + 0], wih[k + 0], a0);
                    a1 = fma2(xp[k + 1], wih[k + 1], a1);
                    a2 = fma2(xp[k + 2], wih[k + 2], a2);
                    a3 = fma2(xp[k + 3], wih[k + 3], a3);
                }
                a0 = fma2(xp[12], wih[12], a0);
                float v = sum2(add2(add2(a0, a1), add2(a2, a3)));
                sg1[tid] = (cls == 2) ? tanh_fast(v) : sigmoid_fast(v);
            }
            BARSYNC();  // B: gates ready
            if (is_upd1) {
                if (t < TT) {
                    int j = tid;
                    float ig = sg1[j] * sg1[128 + j];
                    c1 = __fmaf_rn(sg1[64 + j], c1, ig);
                    sh1[j] = sg1[192 + j] * tanh_fast(c1);
                }
            } else if (is_upd2) {
                if (t > 0) {
                    int j = tid - 64;
                    float ig = sg2[j] * sg2[64 + j];
                    c2 = __fmaf_rn(sg2[32 + j], c2, ig);
                    sh2[j] = sg2[96 + j] * tanh_fast(c2);
                }
            } else if (is_load) {
                if (t + 1 < TT) {
                    sx[(t + 1) & 1][xi] = xreg;
                    if (t + 2 < TT) xreg = x[xbase + (size_t)xi * TT + (t + 2)];
                }
            }
        }

        // ---- FC head (barrier counts matched with layer-2 branch) ----
        BARSYNC();  // D1: sh2 = h2(T-1) ready
        if (tid < 16) {
            float acc = b_fc1[tid];
            #pragma unroll
            for (int k = 0; k < H2; k++) acc = __fmaf_rn(w_fc1[tid * H2 + k], sh2[k], acc);
            sf[tid] = fmaxf(acc, 0.0f);
        }
        BARSYNC();  // D2
        if (tid < 10) {
            float acc = b_fc2[tid];
            #pragma unroll
            for (int k = 0; k < 16; k++) acc = __fmaf_rn(w_fc2[tid * 16 + k], sf[k], acc);
            out[b * 10 + tid] = acc;
        }
    } else {
        // ================= Layer-2 gate thread (lags one step) ===================
        const int g = tid - 256;   // 0..127
        ull wi2[32], wh2[16];
        {
            const float2* wi = (const float2*)(w_ih2 + g * H1);
            #pragma unroll
            for (int k = 0; k < 32; k++) { float2 v = wi[k]; wi2[k] = pack2(v.x, v.y); }
            const float2* wh = (const float2*)(w_hh2 + g * H2);
            #pragma unroll
            for (int k = 0; k < 16; k++) { float2 v = wh[k]; wh2[k] = pack2(v.x, v.y); }
        }
        const float bias2 = b_ih2[g] + b_hh2[g];
        const int   cls2  = g >> 5;   // uniform per warp

        #pragma unroll 1
        for (int t = 0; t <= TT; t++) {
            BARSYNC();  // A
            if (t > 0) {
                // gates for s = t-1: uses h1(t-1) (=sh1 now) and h2(t-2) (=sh2 now)
                ull a0 = pack2(bias2, 0.0f), a1 = 0ull, a2 = 0ull, a3 = 0ull;
                const ull* hp1 = (const ull*)sh1;
                #pragma unroll
                for (int k = 0; k < 32; k += 4) {
                    a0 = fma2(hp1[k + 0], wi2[k + 0], a0);
                    a1 = fma2(hp1[k + 1], wi2[k + 1], a1);
                    a2 = fma2(hp1[k + 2], wi2[k + 2], a2);
                    a3 = fma2(hp1[k + 3], wi2[k + 3], a3);
                }
                const ull* hp2 = (const ull*)sh2;
                #pragma unroll
                for (int k = 0; k < 16; k += 4) {
                    a0 = fma2(hp2[k + 0], wh2[k + 0], a0);
                    a1 = fma2(hp2[k + 1], wh2[k + 1], a1);
                    a2 = fma2(hp2[k + 2], wh2[k + 2], a2);
                    a3 = fma2(hp2[k + 3], wh2[k + 3], a3);
                }
                float v = sum2(add2(add2(a0, a1), add2(a2, a3)));
                sg2[g] = (cls2 == 2) ? tanh_fast(v) : sigmoid_fast(v);
            }
            BARSYNC();  // B
            // no phase-2 work in this branch
        }
        BARSYNC();  // D1
        BARSYNC();  // D2
    }
}

extern "C" void kernel_launch(void* const* d_in, const int* in_sizes, int n_in,
                              void* d_out, int out_size)
{
    const float* x     = (const float*)d_in[0];
    const float* w_ih1 = (const float*)d_in[1];
    const float* w_hh1 = (const float*)d_in[2];
    const float* b_ih1 = (const float*)d_in[3];
    const float* b_hh1 = (const float*)d_in[4];
    const float* w_ih2 = (const float*)d_in[5];
    const float* w_hh2 = (const float*)d_in[6];
    const float* b_ih2 = (const float*)d_in[7];
    const float* b_hh2 = (const float*)d_in[8];
    const float* w_fc1 = (const float*)d_in[9];
    const float* b_fc1 = (const float*)d_in[10];
    const float* w_fc2 = (const float*)d_in[11];
    const float* b_fc2 = (const float*)d_in[12];
    float* out = (float*)d_out;

    audiolstm_kernel<<<NB, NTHREADS>>>(x, w_ih1, w_hh1, b_ih1, b_hh1,
                                       w_ih2, w_hh2, b_ih2, b_hh2,
                                       w_fc1, b_fc1, w_fc2, b_fc2, out);
}

// round 7
// speedup vs baseline: 1.2211x; 1.2211x over previous
#include <cuda_runtime.h>

// AudioLSTM: 2-layer LSTM (26 -> 64 -> 32) over T=1000, B=512, + FC 32->16->10.
// 4 batch elements per CTA (128 CTAs, single wave). Weights register-resident,
// reused across the 4 batches. fma.rn.f32x2 packed math. Layer 2 lags layer 1
// by one step -> 2 barriers per timestep, amortized over 4 batches.

#define IN   26
#define H1   64
#define H2   32
#define NB   512
#define TT   1000
#define BPC  4              // batches per CTA
#define NTHREADS 384

typedef unsigned long long ull;

__device__ __forceinline__ ull pack2(float lo, float hi) {
    ull r;
    asm("mov.b64 %0, {%1, %2};" : "=l"(r) : "f"(lo), "f"(hi));
    return r;
}
__device__ __forceinline__ float sum2(ull a) {
    float lo, hi;
    asm("mov.b64 {%0, %1}, %2;" : "=f"(lo), "=f"(hi) : "l"(a));
    return lo + hi;
}
__device__ __forceinline__ ull fma2(ull a, ull b, ull c) {
    ull d;
    asm("fma.rn.f32x2 %0, %1, %2, %3;" : "=l"(d) : "l"(a), "l"(b), "l"(c));
    return d;
}
__device__ __forceinline__ ull add2(ull a, ull b) {
    ull d;
    asm("add.rn.f32x2 %0, %1, %2;" : "=l"(d) : "l"(a), "l"(b));
    return d;
}

#define BARSYNC() asm volatile("bar.sync 0;" ::: "memory")

__device__ __forceinline__ float sigmoid_fast(float x) {
    float e = __expf(-x);
    return __fdividef(1.0f, 1.0f + e);
}
__device__ __forceinline__ float tanh_fast(float x) {
    float e = __expf(-2.0f * x);
    return __fmaf_rn(2.0f, __fdividef(1.0f, 1.0f + e), -1.0f);
}

__global__ void __launch_bounds__(NTHREADS, 1)
audiolstm_kernel(const float* __restrict__ x,
                 const float* __restrict__ w_ih1, const float* __restrict__ w_hh1,
                 const float* __restrict__ b_ih1, const float* __restrict__ b_hh1,
                 const float* __restrict__ w_ih2, const float* __restrict__ w_hh2,
                 const float* __restrict__ b_ih2, const float* __restrict__ b_hh2,
                 const float* __restrict__ w_fc1, const float* __restrict__ b_fc1,
                 const float* __restrict__ w_fc2, const float* __restrict__ b_fc2,
                 float* __restrict__ out)
{
    const int b0  = blockIdx.x * BPC;
    const int tid = threadIdx.x;

    __shared__ __align__(16) float sh1[BPC][H1];        // h1(t) per batch
    __shared__ __align__(16) float sh2[BPC][H2];        // h2(t) per batch
    __shared__ __align__(16) float sg1[BPC][4 * H1];    // activated gates, layer 1
    __shared__ __align__(16) float sg2[BPC][4 * H2];    // activated gates, layer 2
    __shared__ __align__(16) float sx[BPC][2][IN + 2];  // x(t) double buffers
    __shared__ __align__(16) float sf[BPC][16];         // fc1 outputs

    // ---- init (before first barrier) ----
    if (tid < BPC * H1) sh1[tid >> 6][tid & 63] = 0.0f;
    if (tid < BPC * H2) sh2[tid >> 5][tid & 31] = 0.0f;

    // x loader role: threads 0..103, one (batch, channel) each
    const bool is_load = (tid < BPC * IN);
    const int  bbx = tid / IN;            // 0..3
    const int  xi  = tid - bbx * IN;      // 0..25
    const size_t xldbase = (size_t)(b0 + bbx) * (size_t)(IN * TT) + (size_t)xi * TT;
    float xreg = 0.0f;
    if (is_load) {
        sx[bbx][0][xi] = x[xldbase + 0];
        xreg = x[xldbase + 1];
    }

    if (tid < 256) {
        // ================= Layer-1 gate thread (4 batches) ==============
        ull wih[13], whh[32];
        {
            const float2* wi = (const float2*)(w_ih1 + tid * IN);
            #pragma unroll
            for (int k = 0; k < 13; k++) { float2 v = wi[k]; wih[k] = pack2(v.x, v.y); }
            const float2* wh = (const float2*)(w_hh1 + tid * H1);
            #pragma unroll
            for (int k = 0; k < 32; k++) { float2 v = wh[k]; whh[k] = pack2(v.x, v.y); }
        }
        const float bias = b_ih1[tid] + b_hh1[tid];
        const int   cls  = tid >> 6;            // gate class, uniform per warp

        // phase-2 role: every L1 thread updates one (batch, unit) of h1
        const int ub = tid >> 6;    // batch for update
        const int uj = tid & 63;    // unit
        float c1 = 0.0f;

        #pragma unroll 1
        for (int t = 0; t <= TT; t++) {
            BARSYNC();  // A: sh1(t-1), sh2(t-2), sx[.][t&1] ready
            if (t < TT) {
                #pragma unroll 1
                for (int bb = 0; bb < BPC; bb++) {
                    ull a0 = pack2(bias, 0.0f), a1 = 0ull, a2 = 0ull, a3 = 0ull;
                    const ull* hp = (const ull*)sh1[bb];
                    #pragma unroll
                    for (int k = 0; k < 32; k += 4) {
                        a0 = fma2(hp[k + 0], whh[k + 0], a0);
                        a1 = fma2(hp[k + 1], whh[k + 1], a1);
                        a2 = fma2(hp[k + 2], whh[k + 2], a2);
                        a3 = fma2(hp[k + 3], whh[k + 3], a3);
                    }
                    const ull* xp = (const ull*)sx[bb][t & 1];
                    #pragma unroll
                    for (int k = 0; k < 12; k += 4) {
                        a0 = fma2(xp[k + 0], wih[k + 0], a0);
                        a1 = fma2(xp[k + 1], wih[k + 1], a1);
                        a2 = fma2(xp[k + 2], wih[k + 2], a2);
                        a3 = fma2(xp[k + 3], wih[k + 3], a3);
                    }
                    a0 = fma2(xp[12], wih[12], a0);
                    float v = sum2(add2(add2(a0, a1), add2(a2, a3)));
                    sg1[bb][tid] = (cls == 2) ? tanh_fast(v) : sigmoid_fast(v);
                }
            }
            BARSYNC();  // B: gates ready
            if (t < TT) {
                float ig = sg1[ub][uj] * sg1[ub][128 + uj];
                c1 = __fmaf_rn(sg1[ub][64 + uj], c1, ig);
                sh1[ub][uj] = sg1[ub][192 + uj] * tanh_fast(c1);
            }
            if (is_load) {
                if (t + 1 < TT) {
                    sx[bbx][(t + 1) & 1][xi] = xreg;
                    if (t + 2 < TT) xreg = x[xldbase + (t + 2)];
                }
            }
        }

        // ---- FC head ----
        BARSYNC();  // D1: sh2 holds final h2 per batch
        if (tid < BPC * 16) {
            int fb = tid >> 4, fj = tid & 15;
            float acc = b_fc1[fj];
            #pragma unroll
            for (int k = 0; k < H2; k++) acc = __fmaf_rn(w_fc1[fj * H2 + k], sh2[fb][k], acc);
            sf[fb][fj] = fmaxf(acc, 0.0f);
        }
        BARSYNC();  // D2
        if (tid < BPC * 10) {
            int fb = tid / 10, fj = tid - fb * 10;
            float acc = b_fc2[fj];
            #pragma unroll
            for (int k = 0; k < 16; k++) acc = __fmaf_rn(w_fc2[fj * 16 + k], sf[fb][k], acc);
            out[(b0 + fb) * 10 + fj] = acc;
        }
    } else {
        // ================= Layer-2 gate thread (4 batches, lags one step) ========
        const int g = tid - 256;   // 0..127
        ull wi2[32], wh2[16];
        {
            const float2* wi = (const float2*)(w_ih2 + g * H1);
            #pragma unroll
            for (int k = 0; k < 32; k++) { float2 v = wi[k]; wi2[k] = pack2(v.x, v.y); }
            const float2* wh = (const float2*)(w_hh2 + g * H2);
            #pragma unroll
            for (int k = 0; k < 16; k++) { float2 v = wh[k]; wh2[k] = pack2(v.x, v.y); }
        }
        const float bias2 = b_ih2[g] + b_hh2[g];
        const int   cls2  = g >> 5;   // uniform per warp

        // phase-2 role: each L2 thread updates one (batch, unit) of h2
        const int ub = g >> 5;    // batch
        const int uj = g & 31;    // unit
        float c2 = 0.0f;

        #pragma unroll 1
        for (int t = 0; t <= TT; t++) {
            BARSYNC();  // A
            if (t > 0) {
                // gates for s = t-1: uses h1(t-1) (=sh1 now) and h2(t-2) (=sh2 now)
                #pragma unroll 1
                for (int bb = 0; bb < BPC; bb++) {
                    ull a0 = pack2(bias2, 0.0f), a1 = 0ull, a2 = 0ull, a3 = 0ull;
                    const ull* hp1 = (const ull*)sh1[bb];
                    #pragma unroll
                    for (int k = 0; k < 32; k += 4) {
                        a0 = fma2(hp1[k + 0], wi2[k + 0], a0);
                        a1 = fma2(hp1[k + 1], wi2[k + 1], a1);
                        a2 = fma2(hp1[k + 2], wi2[k + 2], a2);
                        a3 = fma2(hp1[k + 3], wi2[k + 3], a3);
                    }
                    const ull* hp2 = (const ull*)sh2[bb];
                    #pragma unroll
                    for (int k = 0; k < 16; k += 4) {
                        a0 = fma2(hp2[k + 0], wh2[k + 0], a0);
                        a1 = fma2(hp2[k + 1], wh2[k + 1], a1);
                        a2 = fma2(hp2[k + 2], wh2[k + 2], a2);
                        a3 = fma2(hp2[k + 3], wh2[k + 3], a3);
                    }
                    float v = sum2(add2(add2(a0, a1), add2(a2, a3)));
                    sg2[bb][g] = (cls2 == 2) ? tanh_fast(v) : sigmoid_fast(v);
                }
            }
            BARSYNC();  // B
            if (t > 0) {
                float ig = sg2[ub][uj] * sg2[ub][64 + uj];
                c2 = __fmaf_rn(sg2[ub][32 + uj], c2, ig);
                sh2[ub][uj] = sg2[ub][96 + uj] * tanh_fast(c2);
            }
        }
        BARSYNC();  // D1
        BARSYNC();  // D2
    }
}

extern "C" void kernel_launch(void* const* d_in, const int* in_sizes, int n_in,
                              void* d_out, int out_size)
{
    const float* x     = (const float*)d_in[0];
    const float* w_ih1 = (const float*)d_in[1];
    const float* w_hh1 = (const float*)d_in[2];
    const float* b_ih1 = (const float*)d_in[3];
    const float* b_hh1 = (const float*)d_in[4];
    const float* w_ih2 = (const float*)d_in[5];
    const float* w_hh2 = (const float*)d_in[6];
    const float* b_ih2 = (const float*)d_in[7];
    const float* b_hh2 = (const float*)d_in[8];
    const float* w_fc1 = (const float*)d_in[9];
    const float* b_fc1 = (const float*)d_in[10];
    const float* w_fc2 = (const float*)d_in[11];
    const float* b_fc2 = (const float*)d_in[12];
    float* out = (float*)d_out;

    audiolstm_kernel<<<NB / BPC, NTHREADS>>>(x, w_ih1, w_hh1, b_ih1, b_hh1,
                                             w_ih2, w_hh2, b_ih2, b_hh2,
                                             w_fc1, b_fc1, w_fc2, b_fc2, out);
}

// round 9
// speedup vs baseline: 1.3334x; 1.0920x over previous
#include <cuda_runtime.h>

// AudioLSTM: 2-layer LSTM (26 -> 64 -> 32) over T=1000, B=512, + FC 32->16->10.
// 4 batches per CTA (128 CTAs, 1 wave). Weights register-resident.
// Round 8: batch-interleaved inner loops (8 indep FMA chains) + LDS.128
// (ulonglong2) shared reads: halves LDS issue count, hides LDS/MUFU latency.

#define IN   26
#define H1   64
#define H2   32
#define NB   512
#define TT   1000
#define BPC  4
#define NTHREADS 384

typedef unsigned long long ull;

__device__ __forceinline__ ull pack2(float lo, float hi) {
    ull r;
    asm("mov.b64 %0, {%1, %2};" : "=l"(r) : "f"(lo), "f"(hi));
    return r;
}
__device__ __forceinline__ float sum2(ull a) {
    float lo, hi;
    asm("mov.b64 {%0, %1}, %2;" : "=f"(lo), "=f"(hi) : "l"(a));
    return lo + hi;
}
__device__ __forceinline__ ull fma2(ull a, ull b, ull c) {
    ull d;
    asm("fma.rn.f32x2 %0, %1, %2, %3;" : "=l"(d) : "l"(a), "l"(b), "l"(c));
    return d;
}
__device__ __forceinline__ ull add2(ull a, ull b) {
    ull d;
    asm("add.rn.f32x2 %0, %1, %2;" : "=l"(d) : "l"(a), "l"(b));
    return d;
}

#define BARSYNC() asm volatile("bar.sync 0;" ::: "memory")

__device__ __forceinline__ float sigmoid_fast(float x) {
    float e = __expf(-x);
    return __fdividef(1.0f, 1.0f + e);
}
__device__ __forceinline__ float tanh_fast(float x) {
    float e = __expf(-2.0f * x);
    return __fmaf_rn(2.0f, __fdividef(1.0f, 1.0f + e), -1.0f);
}

__global__ void __launch_bounds__(NTHREADS, 1)
audiolstm_kernel(const float* __restrict__ x,
                 const float* __restrict__ w_ih1, const float* __restrict__ w_hh1,
                 const float* __restrict__ b_ih1, const float* __restrict__ b_hh1,
                 const float* __restrict__ w_ih2, const float* __restrict__ w_hh2,
                 const float* __restrict__ b_ih2, const float* __restrict__ b_hh2,
                 const float* __restrict__ w_fc1, const float* __restrict__ b_fc1,
                 const float* __restrict__ w_fc2, const float* __restrict__ b_fc2,
                 float* __restrict__ out)
{
    const int b0  = blockIdx.x * BPC;
    const int tid = threadIdx.x;

    __shared__ __align__(16) float sh1[BPC][H1];        // h1(t)
    __shared__ __align__(16) float sh2[BPC][H2];        // h2(t)
    __shared__ __align__(16) float sg1[BPC][4 * H1];    // activated gates L1
    __shared__ __align__(16) float sg2[BPC][4 * H2];    // activated gates L2
    __shared__ __align__(16) float sx[BPC][2][IN + 2];  // x double buffer (pad=0)
    __shared__ __align__(16) float sf[BPC][16];

    // ---- init ----
    if (tid < BPC * H1) sh1[tid >> 6][tid & 63] = 0.0f;
    if (tid < BPC * H2) sh2[tid >> 5][tid & 31] = 0.0f;
    if (tid < BPC * 4) {   // zero the 2-float pads of both x buffers
        int bb = tid >> 2, buf = (tid >> 1) & 1, i = IN + (tid & 1);
        sx[bb][buf][i] = 0.0f;
    }

    const bool is_load = (tid < BPC * IN);
    const int  bbx = tid / IN;
    const int  xi  = tid - bbx * IN;
    const size_t xldbase = (size_t)(b0 + bbx) * (size_t)(IN * TT) + (size_t)xi * TT;
    float xreg = 0.0f;
    if (is_load) {
        sx[bbx][0][xi] = x[xldbase + 0];
        xreg = x[xldbase + 1];
    }

    if (tid < 256) {
        // ================= Layer-1 gate thread ==============
        ull whh[32];     // 16 chunks of 16B over H1=64
        ull wih[14];     // 7 chunks over IN(+pad)=28; wih[13]=0
        {
            const float2* wh = (const float2*)(w_hh1 + tid * H1);
            #pragma unroll
            for (int k = 0; k < 32; k++) { float2 v = wh[k]; whh[k] = pack2(v.x, v.y); }
            const float2* wi = (const float2*)(w_ih1 + tid * IN);
            #pragma unroll
            for (int k = 0; k < 13; k++) { float2 v = wi[k]; wih[k] = pack2(v.x, v.y); }
            wih[13] = 0ull;
        }
        const float bias = b_ih1[tid] + b_hh1[tid];
        const int   cls  = tid >> 6;        // uniform per warp

        const int ub = tid >> 6;            // phase-2: (batch, unit)
        const int uj = tid & 63;
        float c1 = 0.0f;

        #pragma unroll 1
        for (int t = 0; t <= TT; t++) {
            BARSYNC();  // A: sh1(t-1), sh2(t-2), sx[.][t&1] ready
            if (t < TT) {
                ull acc0[BPC], acc1[BPC];
                #pragma unroll
                for (int bb = 0; bb < BPC; bb++) {
                    acc0[bb] = pack2(bias, 0.0f);
                    acc1[bb] = 0ull;
                }
                // h part: 16 chunks x 4 batches, interleaved
                #pragma unroll
                for (int k = 0; k < 16; k++) {
                    #pragma unroll
                    for (int bb = 0; bb < BPC; bb++) {
                        ulonglong2 v = ((const ulonglong2*)sh1[bb])[k];
                        acc0[bb] = fma2(v.x, whh[2 * k + 0], acc0[bb]);
                        acc1[bb] = fma2(v.y, whh[2 * k + 1], acc1[bb]);
                    }
                }
                // x part: 7 chunks x 4 batches
                const int buf = t & 1;
                #pragma unroll
                for (int k = 0; k < 7; k++) {
                    #pragma unroll
                    for (int bb = 0; bb < BPC; bb++) {
                        ulonglong2 v = ((const ulonglong2*)sx[bb][buf])[k];
                        acc0[bb] = fma2(v.x, wih[2 * k + 0], acc0[bb]);
                        acc1[bb] = fma2(v.y, wih[2 * k + 1], acc1[bb]);
                    }
                }
                #pragma unroll
                for (int bb = 0; bb < BPC; bb++) {
                    float v = sum2(add2(acc0[bb], acc1[bb]));
                    sg1[bb][tid] = (cls == 2) ? tanh_fast(v) : sigmoid_fast(v);
                }
            }
            BARSYNC();  // B: gates ready
            if (t < TT) {
                float ig = sg1[ub][uj] * sg1[ub][128 + uj];
                c1 = __fmaf_rn(sg1[ub][64 + uj], c1, ig);
                sh1[ub][uj] = sg1[ub][192 + uj] * tanh_fast(c1);
            }
            if (is_load) {
                if (t + 1 < TT) {
                    sx[bbx][(t + 1) & 1][xi] = xreg;
                    if (t + 2 < TT) xreg = x[xldbase + (t + 2)];
                }
            }
        }

        // ---- FC head ----
        BARSYNC();  // D1
        if (tid < BPC * 16) {
            int fb = tid >> 4, fj = tid & 15;
            float acc = b_fc1[fj];
            #pragma unroll
            for (int k = 0; k < H2; k++) acc = __fmaf_rn(w_fc1[fj * H2 + k], sh2[fb][k], acc);
            sf[fb][fj] = fmaxf(acc, 0.0f);
        }
        BARSYNC();  // D2
        if (tid < BPC * 10) {
            int fb = tid / 10, fj = tid - fb * 10;
            float acc = b_fc2[fj];
            #pragma unroll
            for (int k = 0; k < 16; k++) acc = __fmaf_rn(w_fc2[fj * 16 + k], sf[fb][k], acc);
            out[(b0 + fb) * 10 + fj] = acc;
        }
    } else {
        // ================= Layer-2 gate thread (lags one step) ========
        const int g = tid - 256;
        ull wi2[32], wh2[16];
        {
            const float2* wi = (const float2*)(w_ih2 + g * H1);
            #pragma unroll
            for (int k = 0; k < 32; k++) { float2 v = wi[k]; wi2[k] = pack2(v.x, v.y); }
            const float2* wh = (const float2*)(w_hh2 + g * H2);
            #pragma unroll
            for (int k = 0; k < 16; k++) { float2 v = wh[k]; wh2[k] = pack2(v.x, v.y); }
        }
        const float bias2 = b_ih2[g] + b_hh2[g];
        const int   cls2  = g >> 5;

        const int ub = g >> 5;
        const int uj = g & 31;
        float c2 = 0.0f;

        #pragma unroll 1
        for (int t = 0; t <= TT; t++) {
            BARSYNC();  // A
            if (t > 0) {
                ull acc0[BPC], acc1[BPC];
                #pragma unroll
                for (int bb = 0; bb < BPC; bb++) {
                    acc0[bb] = pack2(bias2, 0.0f);
                    acc1[bb] = 0ull;
                }
                // h1 input: 16 chunks x 4 batches
                #pragma unroll
                for (int k = 0; k < 16; k++) {
                    #pragma unroll
                    for (int bb = 0; bb < BPC; bb++) {
                        ulonglong2 v = ((const ulonglong2*)sh1[bb])[k];
                        acc0[bb] = fma2(v.x, wi2[2 * k + 0], acc0[bb]);
                        acc1[bb] = fma2(v.y, wi2[2 * k + 1], acc1[bb]);
                    }
                }
                // h2 recurrent: 8 chunks x 4 batches
                #pragma unroll
                for (int k = 0; k < 8; k++) {
                    #pragma unroll
                    for (int bb = 0; bb < BPC; bb++) {
                        ulonglong2 v = ((const ulonglong2*)sh2[bb])[k];
                        acc0[bb] = fma2(v.x, wh2[2 * k + 0], acc0[bb]);
                        acc1[bb] = fma2(v.y, wh2[2 * k + 1], acc1[bb]);
                    }
                }
                #pragma unroll
                for (int bb = 0; bb < BPC; bb++) {
                    float v = sum2(add2(acc0[bb], acc1[bb]));
                    sg2[bb][g] = (cls2 == 2) ? tanh_fast(v) : sigmoid_fast(v);
                }
            }
            BARSYNC();  // B
            if (t > 0) {
                float ig = sg2[ub][uj] * sg2[ub][64 + uj];
                c2 = __fmaf_rn(sg2[ub][32 + uj], c2, ig);
                sh2[ub][uj] = sg2[ub][96 + uj] * tanh_fast(c2);
            }
        }
        BARSYNC();  // D1
        BARSYNC();  // D2
    }
}

extern "C" void kernel_launch(void* const* d_in, const int* in_sizes, int n_in,
                              void* d_out, int out_size)
{
    const float* x     = (const float*)d_in[0];
    const float* w_ih1 = (const float*)d_in[1];
    const float* w_hh1 = (const float*)d_in[2];
    const float* b_ih1 = (const float*)d_in[3];
    const float* b_hh1 = (const float*)d_in[4];
    const float* w_ih2 = (const float*)d_in[5];
    const float* w_hh2 = (const float*)d_in[6];
    const float* b_ih2 = (const float*)d_in[7];
    const float* b_hh2 = (const float*)d_in[8];
    const float* w_fc1 = (const float*)d_in[9];
    const float* b_fc1 = (const float*)d_in[10];
    const float* w_fc2 = (const float*)d_in[11];
    const float* b_fc2 = (const float*)d_in[12];
    float* out = (float*)d_out;

    audiolstm_kernel<<<NB / BPC, NTHREADS>>>(x, w_ih1, w_hh1, b_ih1, b_hh1,
                                             w_ih2, w_hh2, b_ih2, b_hh2,
                                             w_fc1, b_fc1, w_fc2, b_fc2, out);
}

// round 11
// speedup vs baseline: 1.4305x; 1.0728x over previous
#include <cuda_runtime.h>

// AudioLSTM: 2-layer LSTM (26 -> 64 -> 32) over T=1000, B=512, + FC 32->16->10.
// Round 10: K-split gate rows across 2 threads -> 768 threads (24 warps) under
// the 85-reg cap. Partial sums combined in phase-2 update threads, which also
// do all activations via MUFU tanh.approx. Biases in smem.

#define IN   26
#define H1   64
#define H2   32
#define NB   512
#define TT   1000
#define BPC  4
#define NT   768

typedef unsigned long long ull;

__device__ __forceinline__ ull pack2(float lo, float hi) {
    ull r;
    asm("mov.b64 %0, {%1, %2};" : "=l"(r) : "f"(lo), "f"(hi));
    return r;
}
__device__ __forceinline__ float sum2(ull a) {
    float lo, hi;
    asm("mov.b64 {%0, %1}, %2;" : "=f"(lo), "=f"(hi) : "l"(a));
    return lo + hi;
}
__device__ __forceinline__ ull fma2(ull a, ull b, ull c) {
    ull d;
    asm("fma.rn.f32x2 %0, %1, %2, %3;" : "=l"(d) : "l"(a), "l"(b), "l"(c));
    return d;
}
__device__ __forceinline__ ull add2(ull a, ull b) {
    ull d;
    asm("add.rn.f32x2 %0, %1, %2;" : "=l"(d) : "l"(a), "l"(b));
    return d;
}

#define BARSYNC() asm volatile("bar.sync 0;" ::: "memory")

__device__ __forceinline__ float tanha(float x) {
    float y;
    asm("tanh.approx.f32 %0, %1;" : "=f"(y) : "f"(x));
    return y;
}
__device__ __forceinline__ float sigm(float x) {
    return __fmaf_rn(0.5f, tanha(0.5f * x), 0.5f);
}

__global__ void __launch_bounds__(NT, 1)
audiolstm_kernel(const float* __restrict__ x,
                 const float* __restrict__ w_ih1, const float* __restrict__ w_hh1,
                 const float* __restrict__ b_ih1, const float* __restrict__ b_hh1,
                 const float* __restrict__ w_ih2, const float* __restrict__ w_hh2,
                 const float* __restrict__ b_ih2, const float* __restrict__ b_hh2,
                 const float* __restrict__ w_fc1, const float* __restrict__ b_fc1,
                 const float* __restrict__ w_fc2, const float* __restrict__ b_fc2,
                 float* __restrict__ out)
{
    const int b0  = blockIdx.x * BPC;
    const int tid = threadIdx.x;

    __shared__ __align__(16) float sh1[BPC][H1];        // h1(t)
    __shared__ __align__(16) float sh2[BPC][H2];        // h2(t)
    __shared__ __align__(16) float sp1[2][BPC][4 * H1]; // L1 gate partials (8KB)
    __shared__ __align__(16) float sp2[2][BPC][4 * H2]; // L2 gate partials (4KB)
    __shared__ __align__(16) float sx[BPC][2][IN + 2];  // x double buffer (pad=0)
    __shared__ __align__(16) float sb1[4 * H1];         // combined biases L1
    __shared__ __align__(16) float sb2[4 * H2];         // combined biases L2
    __shared__ __align__(16) float sf[BPC][16];

    // ---- init (synced by first BAR A) ----
    if (tid < 256) { sh1[tid >> 6][tid & 63] = 0.0f; sb1[tid] = b_ih1[tid] + b_hh1[tid]; }
    if (tid >= 512 && tid < 640) {
        int r = tid - 512;
        sh2[r >> 5][r & 31] = 0.0f;
        sb2[r] = b_ih2[r] + b_hh2[r];
    }
    if (tid >= 640 && tid < 656) {   // zero 2-float pads of both x buffers
        int q = tid - 640;
        sx[q >> 2][(q >> 1) & 1][IN + (q & 1)] = 0.0f;
    }

    if (tid < 256) {
        // ===== L1 half0: h1 chunks 0..11  (+ L1 update role) =====
        ull w[24];
        {
            const float2* wh = (const float2*)(w_hh1 + tid * H1);
            #pragma unroll
            for (int k = 0; k < 24; k++) { float2 v = wh[k]; w[k] = pack2(v.x, v.y); }
        }
        const int ub = tid >> 6, uj = tid & 63;
        float c1 = 0.0f;

        #pragma unroll 1
        for (int t = 0; t <= TT; t++) {
            BARSYNC();  // A
            if (t < TT) {
                ull a0[BPC], a1[BPC];
                #pragma unroll
                for (int bb = 0; bb < BPC; bb++) { a0[bb] = 0ull; a1[bb] = 0ull; }
                #pragma unroll
                for (int k = 0; k < 12; k++) {
                    #pragma unroll
                    for (int bb = 0; bb < BPC; bb++) {
                        ulonglong2 v = ((const ulonglong2*)sh1[bb])[k];
                        a0[bb] = fma2(v.x, w[2 * k + 0], a0[bb]);
                        a1[bb] = fma2(v.y, w[2 * k + 1], a1[bb]);
                    }
                }
                #pragma unroll
                for (int bb = 0; bb < BPC; bb++)
                    sp1[0][bb][tid] = sum2(add2(a0[bb], a1[bb]));
            }
            BARSYNC();  // B
            if (t < TT) {
                float ir = sp1[0][ub][uj]       + sp1[1][ub][uj]       + sb1[uj];
                float fr = sp1[0][ub][64 + uj]  + sp1[1][ub][64 + uj]  + sb1[64 + uj];
                float gr = sp1[0][ub][128 + uj] + sp1[1][ub][128 + uj] + sb1[128 + uj];
                float orr= sp1[0][ub][192 + uj] + sp1[1][ub][192 + uj] + sb1[192 + uj];
                float ig = sigm(ir) * tanha(gr);
                c1 = __fmaf_rn(sigm(fr), c1, ig);
                sh1[ub][uj] = sigm(orr) * tanha(c1);
            }
        }

        // ---- FC head ----
        BARSYNC();  // D1
        if (tid < BPC * 16) {
            int fb = tid >> 4, fj = tid & 15;
            float acc = b_fc1[fj];
            #pragma unroll
            for (int k = 0; k < H2; k++) acc = __fmaf_rn(w_fc1[fj * H2 + k], sh2[fb][k], acc);
            sf[fb][fj] = fmaxf(acc, 0.0f);
        }
        BARSYNC();  // D2
        if (tid < BPC * 10) {
            int fb = tid / 10, fj = tid - fb * 10;
            float acc = b_fc2[fj];
            #pragma unroll
            for (int k = 0; k < 16; k++) acc = __fmaf_rn(w_fc2[fj * 16 + k], sf[fb][k], acc);
            out[(b0 + fb) * 10 + fj] = acc;
        }
    } else if (tid < 512) {
        // ===== L1 half1: h1 chunks 12..15 + x chunks 0..6 =====
        const int g = tid - 256;
        ull w[8], wx[14];
        {
            const float2* wh = (const float2*)(w_hh1 + g * H1);
            #pragma unroll
            for (int k = 0; k < 8; k++) { float2 v = wh[24 + k]; w[k] = pack2(v.x, v.y); }
            const float2* wi = (const float2*)(w_ih1 + g * IN);
            #pragma unroll
            for (int k = 0; k < 13; k++) { float2 v = wi[k]; wx[k] = pack2(v.x, v.y); }
            wx[13] = 0ull;
        }

        #pragma unroll 1
        for (int t = 0; t <= TT; t++) {
            BARSYNC();  // A
            if (t < TT) {
                ull a0[BPC], a1[BPC];
                #pragma unroll
                for (int bb = 0; bb < BPC; bb++) { a0[bb] = 0ull; a1[bb] = 0ull; }
                #pragma unroll
                for (int k = 0; k < 4; k++) {
                    #pragma unroll
                    for (int bb = 0; bb < BPC; bb++) {
                        ulonglong2 v = ((const ulonglong2*)sh1[bb])[12 + k];
                        a0[bb] = fma2(v.x, w[2 * k + 0], a0[bb]);
                        a1[bb] = fma2(v.y, w[2 * k + 1], a1[bb]);
                    }
                }
                const int buf = t & 1;
                #pragma unroll
                for (int k = 0; k < 7; k++) {
                    #pragma unroll
                    for (int bb = 0; bb < BPC; bb++) {
                        ulonglong2 v = ((const ulonglong2*)sx[bb][buf])[k];
                        a0[bb] = fma2(v.x, wx[2 * k + 0], a0[bb]);
                        a1[bb] = fma2(v.y, wx[2 * k + 1], a1[bb]);
                    }
                }
                #pragma unroll
                for (int bb = 0; bb < BPC; bb++)
                    sp1[1][bb][g] = sum2(add2(a0[bb], a1[bb]));
            }
            BARSYNC();  // B
        }
        BARSYNC();  // D1
        BARSYNC();  // D2
    } else if (tid < 640) {
        // ===== L2 half0: h1 chunks 0..11  (+ L2 update role), lags one step =====
        const int g2 = tid - 512;   // 0..127
        ull w[24];
        {
            const float2* wi = (const float2*)(w_ih2 + g2 * H1);
            #pragma unroll
            for (int k = 0; k < 24; k++) { float2 v = wi[k]; w[k] = pack2(v.x, v.y); }
        }
        const int ub = g2 >> 5, uj = g2 & 31;
        float c2 = 0.0f;

        #pragma unroll 1
        for (int t = 0; t <= TT; t++) {
            BARSYNC();  // A
            if (t > 0) {
                ull a0[BPC], a1[BPC];
                #pragma unroll
                for (int bb = 0; bb < BPC; bb++) { a0[bb] = 0ull; a1[bb] = 0ull; }
                #pragma unroll
                for (int k = 0; k < 12; k++) {
                    #pragma unroll
                    for (int bb = 0; bb < BPC; bb++) {
                        ulonglong2 v = ((const ulonglong2*)sh1[bb])[k];
                        a0[bb] = fma2(v.x, w[2 * k + 0], a0[bb]);
                        a1[bb] = fma2(v.y, w[2 * k + 1], a1[bb]);
                    }
                }
                #pragma unroll
                for (int bb = 0; bb < BPC; bb++)
                    sp2[0][bb][g2] = sum2(add2(a0[bb], a1[bb]));
            }
            BARSYNC();  // B
            if (t > 0) {
                float ir = sp2[0][ub][uj]      + sp2[1][ub][uj]      + sb2[uj];
                float fr = sp2[0][ub][32 + uj] + sp2[1][ub][32 + uj] + sb2[32 + uj];
                float gr = sp2[0][ub][64 + uj] + sp2[1][ub][64 + uj] + sb2[64 + uj];
                float orr= sp2[0][ub][96 + uj] + sp2[1][ub][96 + uj] + sb2[96 + uj];
                float ig = sigm(ir) * tanha(gr);
                c2 = __fmaf_rn(sigm(fr), c2, ig);
                sh2[ub][uj] = sigm(orr) * tanha(c2);
            }
        }
        BARSYNC();  // D1
        BARSYNC();  // D2
    } else {
        // ===== L2 half1: h1 chunks 12..15 + h2 chunks 0..7 (+ x loader) =====
        const int g2 = tid - 640;   // 0..127
        ull wa[8], wb[16];
        {
            const float2* wi = (const float2*)(w_ih2 + g2 * H1);
            #pragma unroll
            for (int k = 0; k < 8; k++) { float2 v = wi[24 + k]; wa[k] = pack2(v.x, v.y); }
            const float2* wh = (const float2*)(w_hh2 + g2 * H2);
            #pragma unroll
            for (int k = 0; k < 16; k++) { float2 v = wh[k]; wb[k] = pack2(v.x, v.y); }
        }
        const bool is_load = (g2 < BPC * IN);
        const int  bbx = is_load ? (g2 / IN) : 0;
        const int  xi  = g2 - bbx * IN;
        const size_t xldbase = (size_t)(b0 + bbx) * (size_t)(IN * TT) + (size_t)xi * TT;
        float xreg = 0.0f;
        if (is_load) {
            sx[bbx][0][xi] = x[xldbase + 0];
            xreg = x[xldbase + 1];
        }

        #pragma unroll 1
        for (int t = 0; t <= TT; t++) {
            BARSYNC();  // A
            if (t > 0) {
                ull a0[BPC], a1[BPC];
                #pragma unroll
                for (int bb = 0; bb < BPC; bb++) { a0[bb] = 0ull; a1[bb] = 0ull; }
                #pragma unroll
                for (int k = 0; k < 4; k++) {
                    #pragma unroll
                    for (int bb = 0; bb < BPC; bb++) {
                        ulonglong2 v = ((const ulonglong2*)sh1[bb])[12 + k];
                        a0[bb] = fma2(v.x, wa[2 * k + 0], a0[bb]);
                        a1[bb] = fma2(v.y, wa[2 * k + 1], a1[bb]);
                    }
                }
                #pragma unroll
                for (int k = 0; k < 8; k++) {
                    #pragma unroll
                    for (int bb = 0; bb < BPC; bb++) {
                        ulonglong2 v = ((const ulonglong2*)sh2[bb])[k];
                        a0[bb] = fma2(v.x, wb[2 * k + 0], a0[bb]);
                        a1[bb] = fma2(v.y, wb[2 * k + 1], a1[bb]);
                    }
                }
                #pragma unroll
                for (int bb = 0; bb < BPC; bb++)
                    sp2[1][bb][g2] = sum2(add2(a0[bb], a1[bb]));
            }
            BARSYNC();  // B
            if (is_load && (t + 1 < TT)) {
                sx[bbx][(t + 1) & 1][xi] = xreg;
                if (t + 2 < TT) xreg = x[xldbase + (t + 2)];
            }
        }
        BARSYNC();  // D1
        BARSYNC();  // D2
    }
}

extern "C" void kernel_launch(void* const* d_in, const int* in_sizes, int n_in,
                              void* d_out, int out_size)
{
    const float* x     = (const float*)d_in[0];
    const float* w_ih1 = (const float*)d_in[1];
    const float* w_hh1 = (const float*)d_in[2];
    const float* b_ih1 = (const float*)d_in[3];
    const float* b_hh1 = (const float*)d_in[4];
    const float* w_ih2 = (const float*)d_in[5];
    const float* w_hh2 = (const float*)d_in[6];
    const float* b_ih2 = (const float*)d_in[7];
    const float* b_hh2 = (const float*)d_in[8];
    const float* w_fc1 = (const float*)d_in[9];
    const float* b_fc1 = (const float*)d_in[10];
    const float* w_fc2 = (const float*)d_in[11];
    const float* b_fc2 = (const float*)d_in[12];
    float* out = (float*)d_out;

    audiolstm_kernel<<<NB / BPC, NT>>>(x, w_ih1, w_hh1, b_ih1, b_hh1,
                                       w_ih2, w_hh2, b_ih2, b_hh2,
                                       w_fc1, b_fc1, w_fc2, b_fc2, out);
}

// round 13
// speedup vs baseline: 1.6736x; 1.1700x over previous
#include <cuda_runtime.h>

// AudioLSTM: 2-layer LSTM (26 -> 64 -> 32) over T=1000, B=512, + FC 32->16->10.
// Round 12: 2 gate rows per thread over a K-quarter -> one smem activation load
// feeds FMAs for BOTH rows (LDS:fma2 = 1:4). 768 threads, ~80 regs. Partials in
// sp[split][batch][row]; update threads combine 4 splits + bias + activations.

#define IN   26
#define H1   64
#define H2   32
#define NB   512
#define TT   1000
#define BPC  4
#define NT   768

typedef unsigned long long ull;

__device__ __forceinline__ ull pack2(float lo, float hi) {
    ull r;
    asm("mov.b64 %0, {%1, %2};" : "=l"(r) : "f"(lo), "f"(hi));
    return r;
}
__device__ __forceinline__ float sum2(ull a) {
    float lo, hi;
    asm("mov.b64 {%0, %1}, %2;" : "=f"(lo), "=f"(hi) : "l"(a));
    return lo + hi;
}
__device__ __forceinline__ ull fma2(ull a, ull b, ull c) {
    ull d;
    asm("fma.rn.f32x2 %0, %1, %2, %3;" : "=l"(d) : "l"(a), "l"(b), "l"(c));
    return d;
}

#define BARSYNC() asm volatile("bar.sync 0;" ::: "memory")

__device__ __forceinline__ float tanha(float x) {
    float y;
    asm("tanh.approx.f32 %0, %1;" : "=f"(y) : "f"(x));
    return y;
}
__device__ __forceinline__ float sigm(float x) {
    return __fmaf_rn(0.5f, tanha(0.5f * x), 0.5f);
}

__global__ void __launch_bounds__(NT, 1)
audiolstm_kernel(const float* __restrict__ x,
                 const float* __restrict__ w_ih1, const float* __restrict__ w_hh1,
                 const float* __restrict__ b_ih1, const float* __restrict__ b_hh1,
                 const float* __restrict__ w_ih2, const float* __restrict__ w_hh2,
                 const float* __restrict__ b_ih2, const float* __restrict__ b_hh2,
                 const float* __restrict__ w_fc1, const float* __restrict__ b_fc1,
                 const float* __restrict__ w_fc2, const float* __restrict__ b_fc2,
                 float* __restrict__ out)
{
    const int b0  = blockIdx.x * BPC;
    const int tid = threadIdx.x;

    __shared__ __align__(16) float sh1[BPC][H1];           // h1(t)
    __shared__ __align__(16) float sh2[BPC][H2];           // h2(t)
    __shared__ __align__(16) float sp1[4][BPC][4 * H1];    // L1 partials [split][b][row] 16KB
    __shared__ __align__(16) float sp2[4][BPC][4 * H2];    // L2 partials 8KB
    __shared__ __align__(16) float sx[BPC][2][32];         // x dbl buffer, floats 26..31 = 0
    __shared__ __align__(16) float sb1[4 * H1];
    __shared__ __align__(16) float sb2[4 * H2];
    __shared__ __align__(16) float sf[BPC][16];

    // ---- init (synced by first BAR A) ----
    if (tid < 256) { sh1[tid >> 6][tid & 63] = 0.0f; sb1[tid] = b_ih1[tid] + b_hh1[tid]; }
    if (tid >= 256 && tid < 384) {
        int r = tid - 256;
        sh2[r >> 5][r & 31] = 0.0f;
        sb2[r] = b_ih2[r] + b_hh2[r];
    }
    if (tid >= 384 && tid < 432) {   // zero x pads: floats 26..31, both buffers, 4 batches
        int q = tid - 384;           // 0..47
        int bb = q / 12, rem = q - bb * 12;
        sx[bb][rem / 6][26 + (rem % 6)] = 0.0f;
    }

    if (tid < 512) {
        // ================= Layer 1: rows {r, r+128}, K-quarter `split` ==========
        const int split = tid >> 7;          // 0..3 (uniform per warp)
        const int r     = tid & 127;
        ull wh[2][8], wx[2][4];
        #pragma unroll
        for (int rr = 0; rr < 2; rr++) {
            const int row = r + rr * 128;
            const float2* ph = (const float2*)(w_hh1 + row * H1 + split * 16);
            #pragma unroll
            for (int k = 0; k < 8; k++) { float2 v = ph[k]; wh[rr][k] = pack2(v.x, v.y); }
            if (split < 3) {
                const float2* px = (const float2*)(w_ih1 + row * IN + split * 8);
                #pragma unroll
                for (int k = 0; k < 4; k++) { float2 v = px[k]; wx[rr][k] = pack2(v.x, v.y); }
            } else {
                const float2* px = (const float2*)(w_ih1 + row * IN + 24);
                float2 v = px[0];
                wx[rr][0] = pack2(v.x, v.y);
                wx[rr][1] = 0ull; wx[rr][2] = 0ull; wx[rr][3] = 0ull;
            }
        }
        const bool upd = (tid < 256);
        const int ub = tid >> 6, uj = tid & 63;
        float c1 = 0.0f;

        #pragma unroll 1
        for (int t = 0; t <= TT; t++) {
            BARSYNC();  // A: sh1(t-1), sh2(t-2), sx[.][t&1] ready
            if (t < TT) {
                ull a0[BPC], a1[BPC];
                #pragma unroll
                for (int bb = 0; bb < BPC; bb++) { a0[bb] = 0ull; a1[bb] = 0ull; }
                // h part: 4 chunks x 4 batches; each chunk feeds both rows
                #pragma unroll
                for (int k = 0; k < 4; k++) {
                    #pragma unroll
                    for (int bb = 0; bb < BPC; bb++) {
                        ulonglong2 v = *(const ulonglong2*)(&sh1[bb][split * 16 + k * 4]);
                        a0[bb] = fma2(v.x, wh[0][2 * k + 0], a0[bb]);
                        a1[bb] = fma2(v.x, wh[1][2 * k + 0], a1[bb]);
                        a0[bb] = fma2(v.y, wh[0][2 * k + 1], a0[bb]);
                        a1[bb] = fma2(v.y, wh[1][2 * k + 1], a1[bb]);
                    }
                }
                // x part: 2 chunks x 4 batches (split3 reads pads, weights 0)
                const int buf = t & 1;
                #pragma unroll
                for (int k = 0; k < 2; k++) {
                    #pragma unroll
                    for (int bb = 0; bb < BPC; bb++) {
                        ulonglong2 v = *(const ulonglong2*)(&sx[bb][buf][split * 8 + k * 4]);
                        a0[bb] = fma2(v.x, wx[0][2 * k + 0], a0[bb]);
                        a1[bb] = fma2(v.x, wx[1][2 * k + 0], a1[bb]);
                        a0[bb] = fma2(v.y, wx[0][2 * k + 1], a0[bb]);
                        a1[bb] = fma2(v.y, wx[1][2 * k + 1], a1[bb]);
                    }
                }
                #pragma unroll
                for (int bb = 0; bb < BPC; bb++) {
                    sp1[split][bb][r]       = sum2(a0[bb]);
                    sp1[split][bb][r + 128] = sum2(a1[bb]);
                }
            }
            BARSYNC();  // B: partials ready
            if (upd && t < TT) {
                float ir = sb1[uj], fr = sb1[64 + uj], gr = sb1[128 + uj], orr = sb1[192 + uj];
                #pragma unroll
                for (int s = 0; s < 4; s++) {
                    ir  += sp1[s][ub][uj];
                    fr  += sp1[s][ub][64 + uj];
                    gr  += sp1[s][ub][128 + uj];
                    orr += sp1[s][ub][192 + uj];
                }
                float ig = sigm(ir) * tanha(gr);
                c1 = __fmaf_rn(sigm(fr), c1, ig);
                sh1[ub][uj] = sigm(orr) * tanha(c1);
            }
        }

        // ---- FC head ----
        BARSYNC();  // D1
        if (tid < BPC * 16) {
            int fb = tid >> 4, fj = tid & 15;
            float acc = b_fc1[fj];
            #pragma unroll
            for (int k = 0; k < H2; k++) acc = __fmaf_rn(w_fc1[fj * H2 + k], sh2[fb][k], acc);
            sf[fb][fj] = fmaxf(acc, 0.0f);
        }
        BARSYNC();  // D2
        if (tid < BPC * 10) {
            int fb = tid / 10, fj = tid - fb * 10;
            float acc = b_fc2[fj];
            #pragma unroll
            for (int k = 0; k < 16; k++) acc = __fmaf_rn(w_fc2[fj * 16 + k], sf[fb][k], acc);
            out[(b0 + fb) * 10 + fj] = acc;
        }
    } else {
        // ================= Layer 2: rows {r2, r2+64}, K-quarter; lags one step ===
        const int q2    = tid - 512;         // 0..255
        const int split = q2 >> 6;           // uniform per warp
        const int r2    = q2 & 63;
        ull wi[2][8], wr[2][4];
        #pragma unroll
        for (int rr = 0; rr < 2; rr++) {
            const int row = r2 + rr * 64;
            const float2* pi = (const float2*)(w_ih2 + row * H1 + split * 16);
            #pragma unroll
            for (int k = 0; k < 8; k++) { float2 v = pi[k]; wi[rr][k] = pack2(v.x, v.y); }
            const float2* pr = (const float2*)(w_hh2 + row * H2 + split * 8);
            #pragma unroll
            for (int k = 0; k < 4; k++) { float2 v = pr[k]; wr[rr][k] = pack2(v.x, v.y); }
        }
        const bool upd = (q2 < 128);
        const int ub = q2 >> 5, uj = q2 & 31;
        float c2 = 0.0f;

        // x loader role: threads 640..743
        const bool is_load = (q2 >= 128 && q2 < 128 + BPC * IN);
        const int  lq  = q2 - 128;
        const int  bbx = is_load ? (lq / IN) : 0;
        const int  xi  = lq - bbx * IN;
        const size_t xldbase = (size_t)(b0 + bbx) * (size_t)(IN * TT) + (size_t)xi * TT;
        float xreg = 0.0f;
        if (is_load) {
            sx[bbx][0][xi] = x[xldbase + 0];
            xreg = x[xldbase + 1];
        }

        #pragma unroll 1
        for (int t = 0; t <= TT; t++) {
            BARSYNC();  // A
            if (t > 0) {
                ull a0[BPC], a1[BPC];
                #pragma unroll
                for (int bb = 0; bb < BPC; bb++) { a0[bb] = 0ull; a1[bb] = 0ull; }
                // h1 input: 4 chunks x 4 batches
                #pragma unroll
                for (int k = 0; k < 4; k++) {
                    #pragma unroll
                    for (int bb = 0; bb < BPC; bb++) {
                        ulonglong2 v = *(const ulonglong2*)(&sh1[bb][split * 16 + k * 4]);
                        a0[bb] = fma2(v.x, wi[0][2 * k + 0], a0[bb]);
                        a1[bb] = fma2(v.x, wi[1][2 * k + 0], a1[bb]);
                        a0[bb] = fma2(v.y, wi[0][2 * k + 1], a0[bb]);
                        a1[bb] = fma2(v.y, wi[1][2 * k + 1], a1[bb]);
                    }
                }
                // h2 recurrent: 2 chunks x 4 batches
                #pragma unroll
                for (int k = 0; k < 2; k++) {
                    #pragma unroll
                    for (int bb = 0; bb < BPC; bb++) {
                        ulonglong2 v = *(const ulonglong2*)(&sh2[bb][split * 8 + k * 4]);
                        a0[bb] = fma2(v.x, wr[0][2 * k + 0], a0[bb]);
                        a1[bb] = fma2(v.x, wr[1][2 * k + 0], a1[bb]);
                        a0[bb] = fma2(v.y, wr[0][2 * k + 1], a0[bb]);
                        a1[bb] = fma2(v.y, wr[1][2 * k + 1], a1[bb]);
                    }
                }
                #pragma unroll
                for (int bb = 0; bb < BPC; bb++) {
                    sp2[split][bb][r2]      = sum2(a0[bb]);
                    sp2[split][bb][r2 + 64] = sum2(a1[bb]);
                }
            }
            BARSYNC();  // B
            if (upd && t > 0) {
                float ir = sb2[uj], fr = sb2[32 + uj], gr = sb2[64 + uj], orr = sb2[96 + uj];
                #pragma unroll
                for (int s = 0; s < 4; s++) {
                    ir  += sp2[s][ub][uj];
                    fr  += sp2[s][ub][32 + uj];
                    gr  += sp2[s][ub][64 + uj];
                    orr += sp2[s][ub][96 + uj];
                }
                float ig = sigm(ir) * tanha(gr);
                c2 = __fmaf_rn(sigm(fr), c2, ig);
                sh2[ub][uj] = sigm(orr) * tanha(c2);
            }
            if (is_load && (t + 1 < TT)) {
                sx[bbx][(t + 1) & 1][xi] = xreg;
                if (t + 2 < TT) xreg = x[xldbase + (t + 2)];
            }
        }
        BARSYNC();  // D1
        BARSYNC();  // D2
    }
}

extern "C" void kernel_launch(void* const* d_in, const int* in_sizes, int n_in,
                              void* d_out, int out_size)
{
    const float* x     = (const float*)d_in[0];
    const float* w_ih1 = (const float*)d_in[1];
    const float* w_hh1 = (const float*)d_in[2];
    const float* b_ih1 = (const float*)d_in[3];
    const float* b_hh1 = (const float*)d_in[4];
    const float* w_ih2 = (const float*)d_in[5];
    const float* w_hh2 = (const float*)d_in[6];
    const float* b_ih2 = (const float*)d_in[7];
    const float* b_hh2 = (const float*)d_in[8];
    const float* w_fc1 = (const float*)d_in[9];
    const float* b_fc1 = (const float*)d_in[10];
    const float* w_fc2 = (const float*)d_in[11];
    const float* b_fc2 = (const float*)d_in[12];
    float* out = (float*)d_out;

    audiolstm_kernel<<<NB / BPC, NT>>>(x, w_ih1, w_hh1, b_ih1, b_hh1,
                                       w_ih2, w_hh2, b_ih2, b_hh2,
                                       w_fc1, b_fc1, w_fc2, b_fc2, out);
}